// round 11
// baseline (speedup 1.0000x reference)
// GAT: factored exp + bitpacked adj -> register scores -> HMMA m16n8k16; smem-staged split-fp16 gemm.
#include <cuda_runtime.h>
#include <cuda_fp16.h>
#include <cstdint>

#define NN 4096
#define NH 4
#define OD 64
#define ID 256
#define NCH 256
#define NTL 9

__device__ float  g_h[NN * ID];
__device__ __half g_r[NH * NN], g_b[NH * NN], g_b2[NH * NN];
__device__ uint2  g_bfrag[NH * NCH * NTL * 32];                // h B-frags (2.25 MB)
__device__ uint4  g_xfh[256 * 16 * 32], g_xfl[256 * 16 * 32];  // x hi/lo A-frags
__device__ uint2  g_wfh[32 * 16 * 32],  g_wfl[32 * 16 * 32];   // W hi/lo B-frags
__device__ unsigned g_adjb[256 * 64 * 32];                     // adj bitpack (2 MB)

__device__ __forceinline__ __half2 u2h(unsigned v) { __half2 h; *(unsigned*)&h = v; return h; }
__device__ __forceinline__ unsigned h2u(__half2 v) { return *(unsigned*)&v; }

__device__ __forceinline__ void split2(float2 v, unsigned& hi, unsigned& lo) {
    __half2 h = __floats2half2_rn(v.x, v.y);
    __half2 l = __floats2half2_rn(v.x - __half2float(__low2half(h)),
                                  v.y - __half2float(__high2half(h)));
    hi = h2u(h); lo = h2u(l);
}

__device__ __forceinline__ void mma16816(float* d, unsigned a0, unsigned a1,
                                         unsigned a2, unsigned a3,
                                         unsigned b0, unsigned b1) {
    asm volatile(
        "mma.sync.aligned.m16n8k16.row.col.f32.f16.f16.f32 "
        "{%0,%1,%2,%3},{%4,%5,%6,%7},{%8,%9},{%0,%1,%2,%3};"
        : "+f"(d[0]), "+f"(d[1]), "+f"(d[2]), "+f"(d[3])
        : "r"(a0), "r"(a1), "r"(a2), "r"(a3), "r"(b0), "r"(b1));
}

// ---- K0a: x -> hi/lo fp16 A-fragments
__global__ void __launch_bounds__(256) k_xfrag(const float* __restrict__ x) {
    int t = blockIdx.x * 256 + threadIdx.x;
    int lane = t & 31, kc = (t >> 5) & 15, rt = t >> 9;
    int r = rt * 16 + (lane >> 2), c = kc * 16 + (lane & 3) * 2;
    float2 v0 = *(const float2*)(x + (size_t)r * ID + c);
    float2 v1 = *(const float2*)(x + (size_t)(r + 8) * ID + c);
    float2 v2 = *(const float2*)(x + (size_t)r * ID + c + 8);
    float2 v3 = *(const float2*)(x + (size_t)(r + 8) * ID + c + 8);
    uint4 h, l;
    split2(v0, h.x, l.x); split2(v1, h.y, l.y);
    split2(v2, h.z, l.z); split2(v3, h.w, l.w);
    g_xfh[t] = h; g_xfl[t] = l;
}

// ---- K0b: W -> hi/lo fp16 B-fragments
__global__ void __launch_bounds__(256) k_wfrag(const float* __restrict__ W) {
    int t = blockIdx.x * 256 + threadIdx.x;
    int lane = t & 31, kc = (t >> 5) & 15, nt = t >> 9;
    int n = nt * 8 + (lane >> 2), k = kc * 16 + (lane & 3) * 2;
    float2 v0 = make_float2(W[(size_t)k * 256 + n], W[(size_t)(k + 1) * 256 + n]);
    float2 v1 = make_float2(W[(size_t)(k + 8) * 256 + n], W[(size_t)(k + 9) * 256 + n]);
    uint2 h, l;
    split2(v0, h.x, l.x); split2(v1, h.y, l.y);
    g_wfh[t] = h; g_wfl[t] = l;
}

// ---- K0c: adj -> bitpack
__global__ void __launch_bounds__(256) k_adjb(const int* __restrict__ adj) {
    int t = blockIdx.x * 256 + threadIdx.x;
    int lane = t & 31, chunk = (t >> 5) & 255, rt = t >> 13;
    int r0 = rt * 16 + (lane >> 2);
    int c = chunk * 16 + (lane & 3) * 2;
    const int2* p = (const int2*)adj;
    int2 v0 = p[((size_t)r0 * NN + c) >> 1];
    int2 v1 = p[((size_t)(r0 + 8) * NN + c) >> 1];
    int2 v2 = p[((size_t)r0 * NN + c + 8) >> 1];
    int2 v3 = p[((size_t)(r0 + 8) * NN + c + 8) >> 1];
    unsigned b = (v0.x & 1) | ((v0.y & 1) << 1) | ((v1.x & 1) << 2) | ((v1.y & 1) << 3)
               | ((v2.x & 1) << 4) | ((v2.y & 1) << 5) | ((v3.x & 1) << 6) | ((v3.y & 1) << 7);
    ((unsigned char*)g_adjb)[(((size_t)rt * 64 + (chunk >> 2)) * 32 + lane) * 4 + (chunk & 3)] =
        (unsigned char)b;
}

// ---- K1: h = x @ W, split-fp16 HMMA with W-frags staged in smem.
// CTA = 4 row-tiles x 32 cols (4 nt); grid = 64 x 8 = 512; 128 threads.
__global__ void __launch_bounds__(128) k_gemm_h3() {
    __shared__ uint4 sw[4 * 16 * 32];   // 32 KB: (hi.x, hi.y, lo.x, lo.y)
    const int lane = threadIdx.x & 31, wid = threadIdx.x >> 5;
    const int rtg = blockIdx.x >> 3, ng = blockIdx.x & 7;
    const int nt0 = ng * 4;
#pragma unroll
    for (int i = threadIdx.x; i < 4 * 16 * 32; i += 128) {
        int l = i & 31, kc = (i >> 5) & 15, nt = i >> 9;
        uint2 hh = g_wfh[(size_t)((nt0 + nt) * 16 + kc) * 32 + l];
        uint2 ll = g_wfl[(size_t)((nt0 + nt) * 16 + kc) * 32 + l];
        sw[i] = make_uint4(hh.x, hh.y, ll.x, ll.y);
    }
    __syncthreads();

    const int rt = rtg * 4 + wid;
    const uint4* ah = g_xfh + (size_t)rt * 16 * 32 + lane;
    const uint4* al = g_xfl + (size_t)rt * 16 * 32 + lane;
    float acc[4][4];
#pragma unroll
    for (int i = 0; i < 4; i++)
#pragma unroll
        for (int j = 0; j < 4; j++) acc[i][j] = 0.f;

    uint4 Ah = ah[0], Al = al[0];
#pragma unroll 4
    for (int kc = 0; kc < 16; kc++) {
        uint4 Ah_n, Al_n;
        if (kc < 15) { Ah_n = ah[(kc + 1) * 32]; Al_n = al[(kc + 1) * 32]; }
#pragma unroll
        for (int nt = 0; nt < 4; nt++) {
            uint4 w = sw[(nt * 16 + kc) * 32 + lane];
            mma16816(acc[nt], Ah.x, Ah.y, Ah.z, Ah.w, w.x, w.y);
            mma16816(acc[nt], Ah.x, Ah.y, Ah.z, Ah.w, w.z, w.w);
            mma16816(acc[nt], Al.x, Al.y, Al.z, Al.w, w.x, w.y);
        }
        Ah = Ah_n; Al = Al_n;
    }

    const int r = rt * 16 + (lane >> 2), c0 = (lane & 3) * 2;
#pragma unroll
    for (int nt = 0; nt < 4; nt++) {
        int col = (nt0 + nt) * 8 + c0;
        *(float2*)&g_h[(size_t)r * ID + col] = make_float2(acc[nt][0], acc[nt][1]);
        *(float2*)&g_h[(size_t)(r + 8) * ID + col] = make_float2(acc[nt][2], acc[nt][3]);
    }
}

// ---- K2a: per-node scores -> exp tables (one warp per node)
__global__ void __launch_bounds__(256) k_etab(const float* __restrict__ att) {
    const int gw = (blockIdx.x * 256 + threadIdx.x) >> 5;
    const int lane = threadIdx.x & 31;
    const float* hr = g_h + (size_t)gw * ID;
#pragma unroll
    for (int h = 0; h < NH; h++) {
        float x0 = hr[h * OD + lane], x1 = hr[h * OD + 32 + lane];
        float s = x0 * att[h * 128 + lane] + x1 * att[h * 128 + 32 + lane];
        float d = x0 * att[h * 128 + 64 + lane] + x1 * att[h * 128 + 96 + lane];
#pragma unroll
        for (int o = 16; o > 0; o >>= 1) {
            s += __shfl_xor_sync(~0u, s, o);
            d += __shfl_xor_sync(~0u, d, o);
        }
        if (lane == 0) {
            g_r [h * NN + gw] = __float2half(expf(-0.8f * s));
            g_b [h * NN + gw] = __float2half(expf(d));
            g_b2[h * NN + gw] = __float2half(expf(0.2f * d));
        }
    }
}

// ---- K2b: h -> B fragments: cols 0..63 = h, col 64 = 1.0, 65..71 = 0
__global__ void __launch_bounds__(256) k_bfrag() {
    int t = blockIdx.x * 256 + threadIdx.x;
    int lane = t & 31, w = t >> 5;
    int nt = w % NTL, chunk = (w / NTL) & 255, head = w / (NTL * 256);
    int k = chunk * 16 + (lane & 3) * 2;
    int n = nt * 8 + (lane >> 2);
    float f0, f1, f2, f3;
    if (n < OD) {
        const float* hp = g_h + head * OD + n;
        f0 = hp[(size_t)k * ID];       f1 = hp[(size_t)(k + 1) * ID];
        f2 = hp[(size_t)(k + 8) * ID]; f3 = hp[(size_t)(k + 9) * ID];
    } else if (n == OD) { f0 = f1 = f2 = f3 = 1.f; }
    else                { f0 = f1 = f2 = f3 = 0.f; }
    g_bfrag[t] = make_uint2(h2u(__floats2half2_rn(f0, f1)), h2u(__floats2half2_rn(f2, f3)));
}

// ---- K3: bitpacked adj -> scores -> HMMA; split-j (2 warps/head) + smem reduction.
__global__ void __launch_bounds__(256, 2) k_attn(float* __restrict__ out) {
    __shared__ float red[4][32][37];
    const int tid = threadIdx.x, wid = tid >> 5, lane = tid & 31;
    const int head = wid & 3, jhalf = wid >> 2;
    const int rt = blockIdx.x;
    const int rlo = rt * 16 + (lane >> 2);
    const int c0 = (lane & 3) * 2;

    const __half2 ra = __half2half2(g_r[head * NN + rlo]);
    const __half2 rb = __half2half2(g_r[head * NN + rlo + 8]);
    const unsigned* adjw = g_adjb + ((size_t)rt * 64 + jhalf * 32) * 32 + lane;
    const uint2* bp0 = g_bfrag + ((size_t)head * NCH + jhalf * 128) * NTL * 32 + lane;
    const __half* pb  = g_b  + head * NN + jhalf * 2048 + c0;
    const __half* pb2 = g_b2 + head * NN + jhalf * 2048 + c0;

    float acc[NTL][4];
#pragma unroll
    for (int i = 0; i < NTL; i++)
#pragma unroll
        for (int j = 0; j < 4; j++) acc[i][j] = 0.f;

#pragma unroll 2
    for (int c4 = 0; c4 < 32; c4++) {
        const unsigned word = adjw[c4 * 32];
#pragma unroll
        for (int j = 0; j < 4; j++) {
            const int ch = c4 * 4 + j;
            const unsigned b = (word >> (8 * j)) & 0xFFu;
            unsigned m00 = (0x3C00u & (0u - (b & 1u)))        | (0x3C000000u & (0u - ((b >> 1) & 1u)));
            unsigned m10 = (0x3C00u & (0u - ((b >> 2) & 1u))) | (0x3C000000u & (0u - ((b >> 3) & 1u)));
            unsigned m01 = (0x3C00u & (0u - ((b >> 4) & 1u))) | (0x3C000000u & (0u - ((b >> 5) & 1u)));
            unsigned m11 = (0x3C00u & (0u - ((b >> 6) & 1u))) | (0x3C000000u & (0u - ((b >> 7) & 1u)));
            __half2 b01 = *(const __half2*)(pb + ch * 16);
            __half2 b89 = *(const __half2*)(pb + ch * 16 + 8);
            __half2 d01 = *(const __half2*)(pb2 + ch * 16);
            __half2 d89 = *(const __half2*)(pb2 + ch * 16 + 8);
            unsigned qa = h2u(__hmul2(u2h(m00), __hmax2(b01, __hmul2(ra, d01))));
            unsigned qb = h2u(__hmul2(u2h(m10), __hmax2(b01, __hmul2(rb, d01))));
            unsigned qc = h2u(__hmul2(u2h(m01), __hmax2(b89, __hmul2(ra, d89))));
            unsigned qd = h2u(__hmul2(u2h(m11), __hmax2(b89, __hmul2(rb, d89))));
            const uint2* bp = bp0 + ch * NTL * 32;
#pragma unroll
            for (int nt = 0; nt < NTL; nt++) {
                uint2 bf = bp[nt * 32];
                mma16816(acc[nt], qa, qb, qc, qd, bf.x, bf.y);
            }
        }
    }

    if (jhalf == 1) {
#pragma unroll
        for (int i = 0; i < NTL; i++)
#pragma unroll
            for (int j = 0; j < 4; j++) red[head][lane][i * 4 + j] = acc[i][j];
    }
    __syncthreads();
    if (jhalf == 0) {
#pragma unroll
        for (int i = 0; i < NTL; i++)
#pragma unroll
            for (int j = 0; j < 4; j++) acc[i][j] += red[head][lane][i * 4 + j];

        float dlo = 1.f / __shfl_sync(~0u, acc[8][0], lane & ~3);
        float dhi = 1.f / __shfl_sync(~0u, acc[8][2], lane & ~3);
        float* o0 = out + (size_t)rlo * (NH * OD) + head * OD;
#pragma unroll
        for (int nt = 0; nt < 8; nt++) {
            int col = nt * 8 + c0;
            *(float2*)(o0 + col) = make_float2(acc[nt][0] * dlo, acc[nt][1] * dlo);
            *(float2*)(o0 + 8 * NH * OD + col) = make_float2(acc[nt][2] * dhi, acc[nt][3] * dhi);
        }
    }
}

extern "C" void kernel_launch(void* const* d_in, const int* in_sizes, int n_in,
                              void* d_out, int out_size) {
    const float* x   = (const float*)d_in[0];
    const int*   adj = (const int*)d_in[1];
    const float* W   = (const float*)d_in[2];
    const float* att = (const float*)d_in[3];
    k_xfrag<<<512, 256>>>(x);
    k_wfrag<<<64, 256>>>(W);
    k_adjb<<<8192, 256>>>(adj);
    k_gemm_h3<<<512, 128>>>();
    k_etab<<<512, 256>>>(att);
    k_bfrag<<<1152, 256>>>();
    k_attn<<<256, 256>>>((float*)d_out);
}

// round 14
// speedup vs baseline: 1.2078x; 1.2078x over previous
// GAT: factored exp + bitpacked adj -> register scores -> HMMA m16n8k16.
// k_attn: per-CTA smem-staged B fragments (4 row-tiles share one B stream).
#include <cuda_runtime.h>
#include <cuda_fp16.h>
#include <cstdint>

#define NN 4096
#define NH 4
#define OD 64
#define ID 256
#define NCH 256
#define NTL 9

__device__ float  g_h[NN * ID];
__device__ __half g_r[NH * NN], g_b[NH * NN], g_b2[NH * NN];
__device__ uint2  g_bfrag[NH * NCH * NTL * 32];                // h B-frags (2.25 MB)
__device__ uint4  g_xfh[256 * 16 * 32], g_xfl[256 * 16 * 32];  // x hi/lo A-frags
__device__ uint2  g_wfh[32 * 16 * 32],  g_wfl[32 * 16 * 32];   // W hi/lo B-frags
__device__ unsigned g_adjb[256 * 64 * 32];                     // adj bitpack (2 MB)

__device__ __forceinline__ __half2 u2h(unsigned v) { __half2 h; *(unsigned*)&h = v; return h; }
__device__ __forceinline__ unsigned h2u(__half2 v) { return *(unsigned*)&v; }

__device__ __forceinline__ void split2(float2 v, unsigned& hi, unsigned& lo) {
    __half2 h = __floats2half2_rn(v.x, v.y);
    __half2 l = __floats2half2_rn(v.x - __half2float(__low2half(h)),
                                  v.y - __half2float(__high2half(h)));
    hi = h2u(h); lo = h2u(l);
}

__device__ __forceinline__ void mma16816(float* d, unsigned a0, unsigned a1,
                                         unsigned a2, unsigned a3,
                                         unsigned b0, unsigned b1) {
    asm volatile(
        "mma.sync.aligned.m16n8k16.row.col.f32.f16.f16.f32 "
        "{%0,%1,%2,%3},{%4,%5,%6,%7},{%8,%9},{%0,%1,%2,%3};"
        : "+f"(d[0]), "+f"(d[1]), "+f"(d[2]), "+f"(d[3])
        : "r"(a0), "r"(a1), "r"(a2), "r"(a3), "r"(b0), "r"(b1));
}

// ---- K0a: x -> hi/lo fp16 A-fragments
__global__ void __launch_bounds__(256) k_xfrag(const float* __restrict__ x) {
    int t = blockIdx.x * 256 + threadIdx.x;
    int lane = t & 31, kc = (t >> 5) & 15, rt = t >> 9;
    int r = rt * 16 + (lane >> 2), c = kc * 16 + (lane & 3) * 2;
    float2 v0 = *(const float2*)(x + (size_t)r * ID + c);
    float2 v1 = *(const float2*)(x + (size_t)(r + 8) * ID + c);
    float2 v2 = *(const float2*)(x + (size_t)r * ID + c + 8);
    float2 v3 = *(const float2*)(x + (size_t)(r + 8) * ID + c + 8);
    uint4 h, l;
    split2(v0, h.x, l.x); split2(v1, h.y, l.y);
    split2(v2, h.z, l.z); split2(v3, h.w, l.w);
    g_xfh[t] = h; g_xfl[t] = l;
}

// ---- K0b: W -> hi/lo fp16 B-fragments
__global__ void __launch_bounds__(256) k_wfrag(const float* __restrict__ W) {
    int t = blockIdx.x * 256 + threadIdx.x;
    int lane = t & 31, kc = (t >> 5) & 15, nt = t >> 9;
    int n = nt * 8 + (lane >> 2), k = kc * 16 + (lane & 3) * 2;
    float2 v0 = make_float2(W[(size_t)k * 256 + n], W[(size_t)(k + 1) * 256 + n]);
    float2 v1 = make_float2(W[(size_t)(k + 8) * 256 + n], W[(size_t)(k + 9) * 256 + n]);
    uint2 h, l;
    split2(v0, h.x, l.x); split2(v1, h.y, l.y);
    g_wfh[t] = h; g_wfl[t] = l;
}

// ---- K0c: adj -> bitpack
__global__ void __launch_bounds__(256) k_adjb(const int* __restrict__ adj) {
    int t = blockIdx.x * 256 + threadIdx.x;
    int lane = t & 31, chunk = (t >> 5) & 255, rt = t >> 13;
    int r0 = rt * 16 + (lane >> 2);
    int c = chunk * 16 + (lane & 3) * 2;
    const int2* p = (const int2*)adj;
    int2 v0 = p[((size_t)r0 * NN + c) >> 1];
    int2 v1 = p[((size_t)(r0 + 8) * NN + c) >> 1];
    int2 v2 = p[((size_t)r0 * NN + c + 8) >> 1];
    int2 v3 = p[((size_t)(r0 + 8) * NN + c + 8) >> 1];
    unsigned b = (v0.x & 1) | ((v0.y & 1) << 1) | ((v1.x & 1) << 2) | ((v1.y & 1) << 3)
               | ((v2.x & 1) << 4) | ((v2.y & 1) << 5) | ((v3.x & 1) << 6) | ((v3.y & 1) << 7);
    ((unsigned char*)g_adjb)[(((size_t)rt * 64 + (chunk >> 2)) * 32 + lane) * 4 + (chunk & 3)] =
        (unsigned char)b;
}

// ---- K1: h = x @ W, split-fp16 HMMA with W-frags staged in smem.
__global__ void __launch_bounds__(128) k_gemm_h3() {
    __shared__ uint4 sw[4 * 16 * 32];   // 32 KB
    const int lane = threadIdx.x & 31, wid = threadIdx.x >> 5;
    const int rtg = blockIdx.x >> 3, ng = blockIdx.x & 7;
    const int nt0 = ng * 4;
#pragma unroll
    for (int i = threadIdx.x; i < 4 * 16 * 32; i += 128) {
        int l = i & 31, kc = (i >> 5) & 15, nt = i >> 9;
        uint2 hh = g_wfh[(size_t)((nt0 + nt) * 16 + kc) * 32 + l];
        uint2 ll = g_wfl[(size_t)((nt0 + nt) * 16 + kc) * 32 + l];
        sw[i] = make_uint4(hh.x, hh.y, ll.x, ll.y);
    }
    __syncthreads();

    const int rt = rtg * 4 + wid;
    const uint4* ah = g_xfh + (size_t)rt * 16 * 32 + lane;
    const uint4* al = g_xfl + (size_t)rt * 16 * 32 + lane;
    float acc[4][4];
#pragma unroll
    for (int i = 0; i < 4; i++)
#pragma unroll
        for (int j = 0; j < 4; j++) acc[i][j] = 0.f;

    uint4 Ah = ah[0], Al = al[0];
#pragma unroll 4
    for (int kc = 0; kc < 16; kc++) {
        uint4 Ah_n, Al_n;
        if (kc < 15) { Ah_n = ah[(kc + 1) * 32]; Al_n = al[(kc + 1) * 32]; }
#pragma unroll
        for (int nt = 0; nt < 4; nt++) {
            uint4 w = sw[(nt * 16 + kc) * 32 + lane];
            mma16816(acc[nt], Ah.x, Ah.y, Ah.z, Ah.w, w.x, w.y);
            mma16816(acc[nt], Ah.x, Ah.y, Ah.z, Ah.w, w.z, w.w);
            mma16816(acc[nt], Al.x, Al.y, Al.z, Al.w, w.x, w.y);
        }
        Ah = Ah_n; Al = Al_n;
    }

    const int r = rt * 16 + (lane >> 2), c0 = (lane & 3) * 2;
#pragma unroll
    for (int nt = 0; nt < 4; nt++) {
        int col = (nt0 + nt) * 8 + c0;
        *(float2*)&g_h[(size_t)r * ID + col] = make_float2(acc[nt][0], acc[nt][1]);
        *(float2*)&g_h[(size_t)(r + 8) * ID + col] = make_float2(acc[nt][2], acc[nt][3]);
    }
}

// ---- K2a: per-node scores -> exp tables (one warp per node)
__global__ void __launch_bounds__(256) k_etab(const float* __restrict__ att) {
    const int gw = (blockIdx.x * 256 + threadIdx.x) >> 5;
    const int lane = threadIdx.x & 31;
    const float* hr = g_h + (size_t)gw * ID;
#pragma unroll
    for (int h = 0; h < NH; h++) {
        float x0 = hr[h * OD + lane], x1 = hr[h * OD + 32 + lane];
        float s = x0 * att[h * 128 + lane] + x1 * att[h * 128 + 32 + lane];
        float d = x0 * att[h * 128 + 64 + lane] + x1 * att[h * 128 + 96 + lane];
#pragma unroll
        for (int o = 16; o > 0; o >>= 1) {
            s += __shfl_xor_sync(~0u, s, o);
            d += __shfl_xor_sync(~0u, d, o);
        }
        if (lane == 0) {
            g_r [h * NN + gw] = __float2half(expf(-0.8f * s));
            g_b [h * NN + gw] = __float2half(expf(d));
            g_b2[h * NN + gw] = __float2half(expf(0.2f * d));
        }
    }
}

// ---- K2b: h -> B fragments: cols 0..63 = h, col 64 = 1.0, 65..71 = 0
__global__ void __launch_bounds__(256) k_bfrag() {
    int t = blockIdx.x * 256 + threadIdx.x;
    int lane = t & 31, w = t >> 5;
    int nt = w % NTL, chunk = (w / NTL) & 255, head = w / (NTL * 256);
    int k = chunk * 16 + (lane & 3) * 2;
    int n = nt * 8 + (lane >> 2);
    float f0, f1, f2, f3;
    if (n < OD) {
        const float* hp = g_h + head * OD + n;
        f0 = hp[(size_t)k * ID];       f1 = hp[(size_t)(k + 1) * ID];
        f2 = hp[(size_t)(k + 8) * ID]; f3 = hp[(size_t)(k + 9) * ID];
    } else if (n == OD) { f0 = f1 = f2 = f3 = 1.f; }
    else                { f0 = f1 = f2 = f3 = 0.f; }
    g_bfrag[t] = make_uint2(h2u(__floats2half2_rn(f0, f1)), h2u(__floats2half2_rn(f2, f3)));
}

// ---- K3: CTA = 1 head x 4 row-tiles x full j; B frags double-buffered in smem.
// Grid = 64 rowgroups x 4 heads = 256 CTAs, 128 threads.
#define GSZ (4 * NTL * 32)   // uint2 per 4-chunk group = 1152
__global__ void __launch_bounds__(128, 2) k_attn(float* __restrict__ out) {
    __shared__ uint2 sB[2][GSZ];   // 2 x 9216 B
    const int tid = threadIdx.x, wid = tid >> 5, lane = tid & 31;
    const int head = blockIdx.x & 3;
    const int rg = blockIdx.x >> 2;
    const int rt = rg * 4 + wid;
    const int rlo = rt * 16 + (lane >> 2);
    const int c0 = (lane & 3) * 2;

    const __half2 ra = __half2half2(g_r[head * NN + rlo]);
    const __half2 rb = __half2half2(g_r[head * NN + rlo + 8]);
    const unsigned* adjw = g_adjb + (size_t)rt * 64 * 32 + lane;
    const uint2* bsrc = g_bfrag + (size_t)head * NCH * NTL * 32;
    const __half* pb  = g_b  + head * NN + c0;
    const __half* pb2 = g_b2 + head * NN + c0;

    float acc[NTL][4];
#pragma unroll
    for (int i = 0; i < NTL; i++)
#pragma unroll
        for (int j = 0; j < 4; j++) acc[i][j] = 0.f;

#pragma unroll
    for (int i = tid; i < GSZ; i += 128) sB[0][i] = bsrc[i];
    __syncthreads();

    for (int g = 0; g < 64; g++) {
        const int buf = g & 1;
        if (g + 1 < 64) {
            const uint2* src = bsrc + (size_t)(g + 1) * GSZ;
#pragma unroll
            for (int i = tid; i < GSZ; i += 128) sB[buf ^ 1][i] = src[i];
        }
        const unsigned word = adjw[g * 32];
#pragma unroll
        for (int j = 0; j < 4; j++) {
            const int ch = g * 4 + j;
            const unsigned b = (word >> (8 * j)) & 0xFFu;
            unsigned m00 = (0x3C00u & (0u - (b & 1u)))        | (0x3C000000u & (0u - ((b >> 1) & 1u)));
            unsigned m10 = (0x3C00u & (0u - ((b >> 2) & 1u))) | (0x3C000000u & (0u - ((b >> 3) & 1u)));
            unsigned m01 = (0x3C00u & (0u - ((b >> 4) & 1u))) | (0x3C000000u & (0u - ((b >> 5) & 1u)));
            unsigned m11 = (0x3C00u & (0u - ((b >> 6) & 1u))) | (0x3C000000u & (0u - ((b >> 7) & 1u)));
            __half2 b01 = *(const __half2*)(pb + ch * 16);
            __half2 b89 = *(const __half2*)(pb + ch * 16 + 8);
            __half2 d01 = *(const __half2*)(pb2 + ch * 16);
            __half2 d89 = *(const __half2*)(pb2 + ch * 16 + 8);
            unsigned qa = h2u(__hmul2(u2h(m00), __hmax2(b01, __hmul2(ra, d01))));
            unsigned qb = h2u(__hmul2(u2h(m10), __hmax2(b01, __hmul2(rb, d01))));
            unsigned qc = h2u(__hmul2(u2h(m01), __hmax2(b89, __hmul2(ra, d89))));
            unsigned qd = h2u(__hmul2(u2h(m11), __hmax2(b89, __hmul2(rb, d89))));
            const uint2* bp = &sB[buf][j * NTL * 32 + lane];
#pragma unroll
            for (int nt = 0; nt < NTL; nt++) {
                uint2 bf = bp[nt * 32];
                mma16816(acc[nt], qa, qb, qc, qd, bf.x, bf.y);
            }
        }
        __syncthreads();
    }

    float dlo = 1.f / __shfl_sync(~0u, acc[8][0], lane & ~3);
    float dhi = 1.f / __shfl_sync(~0u, acc[8][2], lane & ~3);
    float* o0 = out + (size_t)rlo * (NH * OD) + head * OD;
#pragma unroll
    for (int nt = 0; nt < 8; nt++) {
        int col = nt * 8 + c0;
        *(float2*)(o0 + col) = make_float2(acc[nt][0] * dlo, acc[nt][1] * dlo);
        *(float2*)(o0 + 8 * NH * OD + col) = make_float2(acc[nt][2] * dhi, acc[nt][3] * dhi);
    }
}

extern "C" void kernel_launch(void* const* d_in, const int* in_sizes, int n_in,
                              void* d_out, int out_size) {
    const float* x   = (const float*)d_in[0];
    const int*   adj = (const int*)d_in[1];
    const float* W   = (const float*)d_in[2];
    const float* att = (const float*)d_in[3];
    k_xfrag<<<512, 256>>>(x);
    k_wfrag<<<64, 256>>>(W);
    k_adjb<<<8192, 256>>>(adj);
    k_gemm_h3<<<512, 128>>>();
    k_etab<<<512, 256>>>(att);
    k_bfrag<<<1152, 256>>>();
    k_attn<<<256, 128>>>((float*)d_out);
}

// round 17
// speedup vs baseline: 1.2176x; 1.0081x over previous
// GAT: factored exp + bitpacked adj -> register scores -> HMMA m16n8k16.
// R13 design (no tcgen05 — harness targets sm_103 without 'a' features).
#include <cuda_runtime.h>
#include <cuda_fp16.h>
#include <cstdint>

#define NN 4096
#define NH 4
#define OD 64
#define ID 256
#define NCH 256
#define NTL 9

__device__ float  g_h[NN * ID];
__device__ __half g_r[NH * NN], g_b[NH * NN], g_b2[NH * NN];
__device__ uint2  g_bfrag[NH * NCH * NTL * 32];                // h B-frags (2.25 MB)
__device__ uint4  g_xfh[256 * 16 * 32], g_xfl[256 * 16 * 32];  // x hi/lo A-frags
__device__ uint2  g_wfh[32 * 16 * 32],  g_wfl[32 * 16 * 32];   // W hi/lo B-frags
__device__ unsigned g_adjb[256 * 64 * 32];                     // adj bitpack (2 MB)

__device__ __forceinline__ __half2 u2h(unsigned v) { __half2 h; *(unsigned*)&h = v; return h; }
__device__ __forceinline__ unsigned h2u(__half2 v) { return *(unsigned*)&v; }

__device__ __forceinline__ void split2(float2 v, unsigned& hi, unsigned& lo) {
    __half2 h = __floats2half2_rn(v.x, v.y);
    __half2 l = __floats2half2_rn(v.x - __half2float(__low2half(h)),
                                  v.y - __half2float(__high2half(h)));
    hi = h2u(h); lo = h2u(l);
}

__device__ __forceinline__ void mma16816(float* d, unsigned a0, unsigned a1,
                                         unsigned a2, unsigned a3,
                                         unsigned b0, unsigned b1) {
    asm volatile(
        "mma.sync.aligned.m16n8k16.row.col.f32.f16.f16.f32 "
        "{%0,%1,%2,%3},{%4,%5,%6,%7},{%8,%9},{%0,%1,%2,%3};"
        : "+f"(d[0]), "+f"(d[1]), "+f"(d[2]), "+f"(d[3])
        : "r"(a0), "r"(a1), "r"(a2), "r"(a3), "r"(b0), "r"(b1));
}

// ---- K0a: x -> hi/lo fp16 A-fragments
__global__ void __launch_bounds__(256) k_xfrag(const float* __restrict__ x) {
    int t = blockIdx.x * 256 + threadIdx.x;
    int lane = t & 31, kc = (t >> 5) & 15, rt = t >> 9;
    int r = rt * 16 + (lane >> 2), c = kc * 16 + (lane & 3) * 2;
    float2 v0 = *(const float2*)(x + (size_t)r * ID + c);
    float2 v1 = *(const float2*)(x + (size_t)(r + 8) * ID + c);
    float2 v2 = *(const float2*)(x + (size_t)r * ID + c + 8);
    float2 v3 = *(const float2*)(x + (size_t)(r + 8) * ID + c + 8);
    uint4 h, l;
    split2(v0, h.x, l.x); split2(v1, h.y, l.y);
    split2(v2, h.z, l.z); split2(v3, h.w, l.w);
    g_xfh[t] = h; g_xfl[t] = l;
}

// ---- K0b: W -> hi/lo fp16 B-fragments
__global__ void __launch_bounds__(256) k_wfrag(const float* __restrict__ W) {
    int t = blockIdx.x * 256 + threadIdx.x;
    int lane = t & 31, kc = (t >> 5) & 15, nt = t >> 9;
    int n = nt * 8 + (lane >> 2), k = kc * 16 + (lane & 3) * 2;
    float2 v0 = make_float2(W[(size_t)k * 256 + n], W[(size_t)(k + 1) * 256 + n]);
    float2 v1 = make_float2(W[(size_t)(k + 8) * 256 + n], W[(size_t)(k + 9) * 256 + n]);
    uint2 h, l;
    split2(v0, h.x, l.x); split2(v1, h.y, l.y);
    g_wfh[t] = h; g_wfl[t] = l;
}

// ---- K0c: adj -> bitpack
__global__ void __launch_bounds__(256) k_adjb(const int* __restrict__ adj) {
    int t = blockIdx.x * 256 + threadIdx.x;
    int lane = t & 31, chunk = (t >> 5) & 255, rt = t >> 13;
    int r0 = rt * 16 + (lane >> 2);
    int c = chunk * 16 + (lane & 3) * 2;
    const int2* p = (const int2*)adj;
    int2 v0 = p[((size_t)r0 * NN + c) >> 1];
    int2 v1 = p[((size_t)(r0 + 8) * NN + c) >> 1];
    int2 v2 = p[((size_t)r0 * NN + c + 8) >> 1];
    int2 v3 = p[((size_t)(r0 + 8) * NN + c + 8) >> 1];
    unsigned b = (v0.x & 1) | ((v0.y & 1) << 1) | ((v1.x & 1) << 2) | ((v1.y & 1) << 3)
               | ((v2.x & 1) << 4) | ((v2.y & 1) << 5) | ((v3.x & 1) << 6) | ((v3.y & 1) << 7);
    ((unsigned char*)g_adjb)[(((size_t)rt * 64 + (chunk >> 2)) * 32 + lane) * 4 + (chunk & 3)] =
        (unsigned char)b;
}

// ---- K1: h = x @ W, split-fp16 HMMA with W-frags staged in smem.
__global__ void __launch_bounds__(128) k_gemm_h3() {
    __shared__ uint4 sw[4 * 16 * 32];   // 32 KB
    const int lane = threadIdx.x & 31, wid = threadIdx.x >> 5;
    const int rtg = blockIdx.x >> 3, ng = blockIdx.x & 7;
    const int nt0 = ng * 4;
#pragma unroll
    for (int i = threadIdx.x; i < 4 * 16 * 32; i += 128) {
        int l = i & 31, kc = (i >> 5) & 15, nt = i >> 9;
        uint2 hh = g_wfh[(size_t)((nt0 + nt) * 16 + kc) * 32 + l];
        uint2 ll = g_wfl[(size_t)((nt0 + nt) * 16 + kc) * 32 + l];
        sw[i] = make_uint4(hh.x, hh.y, ll.x, ll.y);
    }
    __syncthreads();
    const int rt = rtg * 4 + wid;
    const uint4* ah = g_xfh + (size_t)rt * 16 * 32 + lane;
    const uint4* al = g_xfl + (size_t)rt * 16 * 32 + lane;
    float acc[4][4];
#pragma unroll
    for (int i = 0; i < 4; i++)
#pragma unroll
        for (int j = 0; j < 4; j++) acc[i][j] = 0.f;
    uint4 Ah = ah[0], Al = al[0];
#pragma unroll 4
    for (int kc = 0; kc < 16; kc++) {
        uint4 Ah_n, Al_n;
        if (kc < 15) { Ah_n = ah[(kc + 1) * 32]; Al_n = al[(kc + 1) * 32]; }
#pragma unroll
        for (int nt = 0; nt < 4; nt++) {
            uint4 w = sw[(nt * 16 + kc) * 32 + lane];
            mma16816(acc[nt], Ah.x, Ah.y, Ah.z, Ah.w, w.x, w.y);
            mma16816(acc[nt], Ah.x, Ah.y, Ah.z, Ah.w, w.z, w.w);
            mma16816(acc[nt], Al.x, Al.y, Al.z, Al.w, w.x, w.y);
        }
        Ah = Ah_n; Al = Al_n;
    }
    const int r = rt * 16 + (lane >> 2), c0 = (lane & 3) * 2;
#pragma unroll
    for (int nt = 0; nt < 4; nt++) {
        int col = (nt0 + nt) * 8 + c0;
        *(float2*)&g_h[(size_t)r * ID + col] = make_float2(acc[nt][0], acc[nt][1]);
        *(float2*)&g_h[(size_t)(r + 8) * ID + col] = make_float2(acc[nt][2], acc[nt][3]);
    }
}

// ---- K_mid: exp tables + B fragments (fused; one launch) ----
__global__ void __launch_bounds__(256) k_mid(const float* __restrict__ att) {
    const int blk = blockIdx.x, tid = threadIdx.x;
    if (blk < 512) {                        // etab: one warp per node
        const int gw = blk * 8 + (tid >> 5);
        const int lane = tid & 31;
        const float* hr = g_h + (size_t)gw * ID;
#pragma unroll
        for (int h = 0; h < NH; h++) {
            float x0 = hr[h * OD + lane], x1 = hr[h * OD + 32 + lane];
            float s = x0 * att[h * 128 + lane] + x1 * att[h * 128 + 32 + lane];
            float d = x0 * att[h * 128 + 64 + lane] + x1 * att[h * 128 + 96 + lane];
#pragma unroll
            for (int o = 16; o > 0; o >>= 1) {
                s += __shfl_xor_sync(~0u, s, o);
                d += __shfl_xor_sync(~0u, d, o);
            }
            if (lane == 0) {
                g_r [h * NN + gw] = __float2half(expf(-0.8f * s));
                g_b [h * NN + gw] = __float2half(expf(d));
                g_b2[h * NN + gw] = __float2half(expf(0.2f * d));
            }
        }
    } else {                                // bfrag: cols 0..63 = h, 64 = 1.0, 65..71 = 0
        int t = (blk - 512) * 256 + tid;
        int lane = t & 31, w = t >> 5;
        int nt = w % NTL, chunk = (w / NTL) & 255, head = w / (NTL * 256);
        int k = chunk * 16 + (lane & 3) * 2;
        int n = nt * 8 + (lane >> 2);
        float f0, f1, f2, f3;
        if (n < OD) {
            const float* hp = g_h + head * OD + n;
            f0 = hp[(size_t)k * ID];       f1 = hp[(size_t)(k + 1) * ID];
            f2 = hp[(size_t)(k + 8) * ID]; f3 = hp[(size_t)(k + 9) * ID];
        } else if (n == OD) { f0 = f1 = f2 = f3 = 1.f; }
        else                { f0 = f1 = f2 = f3 = 0.f; }
        g_bfrag[t] = make_uint2(h2u(__floats2half2_rn(f0, f1)), h2u(__floats2half2_rn(f2, f3)));
    }
}

// ---- K3: CTA = 1 head x 4 row-tiles x full j; B frags double-buffered in smem.
#define GSZ (4 * NTL * 32)   // uint2 per 4-chunk group = 1152
__global__ void __launch_bounds__(128, 3) k_attn(float* __restrict__ out) {
    __shared__ uint2 sB[2][GSZ];   // 2 x 9216 B
    const int tid = threadIdx.x, wid = tid >> 5, lane = tid & 31;
    const int head = blockIdx.x & 3;
    const int rg = blockIdx.x >> 2;
    const int rt = rg * 4 + wid;
    const int rlo = rt * 16 + (lane >> 2);
    const int c0 = (lane & 3) * 2;

    const __half2 ra = __half2half2(g_r[head * NN + rlo]);
    const __half2 rb = __half2half2(g_r[head * NN + rlo + 8]);
    const unsigned* adjw = g_adjb + (size_t)rt * 64 * 32 + lane;
    const uint2* bsrc = g_bfrag + (size_t)head * NCH * NTL * 32;
    const __half* pb  = g_b  + head * NN + c0;
    const __half* pb2 = g_b2 + head * NN + c0;

    float acc[NTL][4];
#pragma unroll
    for (int i = 0; i < NTL; i++)
#pragma unroll
        for (int j = 0; j < 4; j++) acc[i][j] = 0.f;

#pragma unroll
    for (int i = tid; i < GSZ; i += 128) sB[0][i] = bsrc[i];
    __syncthreads();

    for (int g = 0; g < 64; g++) {
        const int buf = g & 1;
        if (g + 1 < 64) {
            const uint2* src = bsrc + (size_t)(g + 1) * GSZ;
#pragma unroll
            for (int i = tid; i < GSZ; i += 128) sB[buf ^ 1][i] = src[i];
        }
        const unsigned word = adjw[g * 32];
#pragma unroll
        for (int j = 0; j < 4; j++) {
            const int ch = g * 4 + j;
            const unsigned b = (word >> (8 * j)) & 0xFFu;
            unsigned m00 = (0x3C00u & (0u - (b & 1u)))        | (0x3C000000u & (0u - ((b >> 1) & 1u)));
            unsigned m10 = (0x3C00u & (0u - ((b >> 2) & 1u))) | (0x3C000000u & (0u - ((b >> 3) & 1u)));
            unsigned m01 = (0x3C00u & (0u - ((b >> 4) & 1u))) | (0x3C000000u & (0u - ((b >> 5) & 1u)));
            unsigned m11 = (0x3C00u & (0u - ((b >> 6) & 1u))) | (0x3C000000u & (0u - ((b >> 7) & 1u)));
            __half2 b01 = *(const __half2*)(pb + ch * 16);
            __half2 b89 = *(const __half2*)(pb + ch * 16 + 8);
            __half2 d01 = *(const __half2*)(pb2 + ch * 16);
            __half2 d89 = *(const __half2*)(pb2 + ch * 16 + 8);
            unsigned qa = h2u(__hmul2(u2h(m00), __hmax2(b01, __hmul2(ra, d01))));
            unsigned qb = h2u(__hmul2(u2h(m10), __hmax2(b01, __hmul2(rb, d01))));
            unsigned qc = h2u(__hmul2(u2h(m01), __hmax2(b89, __hmul2(ra, d89))));
            unsigned qd = h2u(__hmul2(u2h(m11), __hmax2(b89, __hmul2(rb, d89))));
            const uint2* bp = &sB[buf][j * NTL * 32 + lane];
#pragma unroll
            for (int nt = 0; nt < NTL; nt++) {
                uint2 bf = bp[nt * 32];
                mma16816(acc[nt], qa, qb, qc, qd, bf.x, bf.y);
            }
        }
        __syncthreads();
    }

    float dlo = 1.f / __shfl_sync(~0u, acc[8][0], lane & ~3);
    float dhi = 1.f / __shfl_sync(~0u, acc[8][2], lane & ~3);
    float* o0 = out + (size_t)rlo * (NH * OD) + head * OD;
#pragma unroll
    for (int nt = 0; nt < 8; nt++) {
        int col = nt * 8 + c0;
        *(float2*)(o0 + col) = make_float2(acc[nt][0] * dlo, acc[nt][1] * dlo);
        *(float2*)(o0 + 8 * NH * OD + col) = make_float2(acc[nt][2] * dhi, acc[nt][3] * dhi);
    }
}

extern "C" void kernel_launch(void* const* d_in, const int* in_sizes, int n_in,
                              void* d_out, int out_size) {
    const float* x   = (const float*)d_in[0];
    const int*   adj = (const int*)d_in[1];
    const float* W   = (const float*)d_in[2];
    const float* att = (const float*)d_in[3];
    // exactly 6 launches; k_attn is launch #6 so ncu (-s 5 -c 1) captures it.
    k_xfrag<<<512, 256>>>(x);
    k_wfrag<<<64, 256>>>(W);
    k_adjb<<<8192, 256>>>(adj);
    k_gemm_h3<<<512, 128>>>();
    k_mid<<<1664, 256>>>(att);
    k_attn<<<256, 128>>>((float*)d_out);
}